// round 3
// baseline (speedup 1.0000x reference)
#include <cuda_runtime.h>

#define BATCH 4
#define DIMC 256
#define MIDC 128
#define HH 128
#define WW 128
#define EPSV 1e-5f

typedef unsigned long long u64;

__device__ __forceinline__ u64 pack2(float lo, float hi) {
    u64 r;
    asm("mov.b64 %0, {%1, %2};" : "=l"(r) : "f"(lo), "f"(hi));
    return r;
}
__device__ __forceinline__ void unpack2(u64 v, float& lo, float& hi) {
    asm("mov.b64 {%0, %1}, %2;" : "=f"(lo), "=f"(hi) : "l"(v));
}
__device__ __forceinline__ void fma2(u64& d, u64 a, u64 b) {
    asm("fma.rn.f32x2 %0, %1, %2, %0;" : "+l"(d) : "l"(a), "l"(b));
}

// Scratch (device globals: allocation-free)
__device__ float g_colmax[BATCH * MIDC * WW];
__device__ float g_rowmax[BATCH * MIDC * HH];
__device__ float g_r[(size_t)BATCH * DIMC * HH * WW];

__global__ void init_max_kernel() {
    int i = blockIdx.x * blockDim.x + threadIdx.x;
    if (i < BATCH * MIDC * WW) {
        g_colmax[i] = 0.f;
        g_rowmax[i] = 0.f;
    }
}

// 3x3 conv (pad=1) + BN + ReLU. Tile: 8 rows x 128 cols, 8 couts per block.
// Each thread: 8 contiguous pixels x 8 couts (32 u64 f32x2 accumulators).
// mode 0: column max (over h) -> out ; mode 1: row max (over w) -> out ;
// mode 2: store NCHW.
__global__ __launch_bounds__(128)
void conv3_kernel(const float* __restrict__ in, const float* __restrict__ wgt,
                  const float* __restrict__ gamma, const float* __restrict__ beta,
                  const float* __restrict__ mean, const float* __restrict__ var,
                  int CIN, int COUT, int mode, float* __restrict__ out)
{
    __shared__ float sIn[4 * 10 * 132];          // 4 ci x 10 rows x 132 (halo+pad)
    __shared__ ulonglong2 sWp[8][4][3];          // (dx0,dx1) dup-u64 pairs
    __shared__ u64 sW2[8][4][3];                 // dx2
    __shared__ float sSc[8], sSh[8];
    __shared__ int sMax[8][128];

    const int h0 = blockIdx.x * 8;
    const int co0 = blockIdx.y * 8;
    const int b = blockIdx.z;
    const int xx = threadIdx.x, yy = threadIdx.y;
    const int tid = yy * 16 + xx;
    const int px = xx * 8;   // first pixel (w) handled by this thread

    if (tid < 8) {
        int c = co0 + tid;
        float sc = gamma[c] * rsqrtf(var[c] + EPSV);
        sSc[tid] = sc;
        sSh[tid] = beta[c] - mean[c] * sc;
    }
    for (int i = tid; i < 1024; i += 128) ((int*)sMax)[i] = 0;
    __syncthreads();

    u64 acc[8][4];
#pragma unroll
    for (int co = 0; co < 8; co++)
#pragma unroll
        for (int q = 0; q < 4; q++) acc[co][q] = 0ULL;

    const float* inb = in + (size_t)b * CIN * HH * WW;

    for (int ci0 = 0; ci0 < CIN; ci0 += 4) {
        // input tile fill (scalar, predicated zero halo)
        for (int idx = tid; idx < 5280; idx += 128) {
            int ci = idx / 1320, r = idx % 1320;
            int hh = r / 132, c = r % 132;
            int gh = h0 - 1 + hh, gw = c - 1;
            float v = 0.f;
            if ((unsigned)gh < (unsigned)HH && (unsigned)gw < (unsigned)WW)
                v = inb[(size_t)(ci0 + ci) * HH * WW + gh * WW + gw];
            sIn[idx] = v;
        }
        // weights (BN-scaled, duplicated halves, pair layout)
        for (int idx = tid; idx < 288; idx += 128) {
            int co = idx / 36, r = idx % 36, ci = r / 9, k = r % 9;
            int dy = k / 3, dx = k % 3;
            float w = wgt[((size_t)(co0 + co) * CIN + ci0 + ci) * 9 + k] * sSc[co];
            u64 d = pack2(w, w);
            if (dx == 2) sW2[co][ci][dy] = d;
            else ((u64*)&sWp[co][ci][dy])[dx] = d;
        }
        __syncthreads();

        for (int ci = 0; ci < 4; ci++) {
#pragma unroll
            for (int dy = 0; dy < 3; dy++) {
                const float* rp = &sIn[ci * 1320 + (yy + dy) * 132 + px];
                float4 va = *(const float4*)rp;
                float4 vb = *(const float4*)(rp + 4);
                float2 vc = *(const float2*)(rp + 8);
                u64 a0[4], a1[4], a2[4];
                a0[0] = pack2(va.x, va.y); a0[1] = pack2(va.z, va.w);
                a0[2] = pack2(vb.x, vb.y); a0[3] = pack2(vb.z, vb.w);
                a1[0] = pack2(va.y, va.z); a1[1] = pack2(va.w, vb.x);
                a1[2] = pack2(vb.y, vb.z); a1[3] = pack2(vb.w, vc.x);
                a2[0] = pack2(va.z, va.w); a2[1] = pack2(vb.x, vb.y);
                a2[2] = pack2(vb.z, vb.w); a2[3] = pack2(vc.x, vc.y);
#pragma unroll
                for (int co = 0; co < 8; co++) {
                    ulonglong2 wp = sWp[co][ci][dy];
                    u64 w2 = sW2[co][ci][dy];
#pragma unroll
                    for (int q = 0; q < 4; q++) {
                        fma2(acc[co][q], wp.x, a0[q]);
                        fma2(acc[co][q], wp.y, a1[q]);
                        fma2(acc[co][q], w2, a2[q]);
                    }
                }
            }
        }
        __syncthreads();
    }

    if (mode == 2) {
#pragma unroll
        for (int co = 0; co < 8; co++) {
            float v[8];
            unpack2(acc[co][0], v[0], v[1]);
            unpack2(acc[co][1], v[2], v[3]);
            unpack2(acc[co][2], v[4], v[5]);
            unpack2(acc[co][3], v[6], v[7]);
            float4 o0, o1;
            o0.x = fmaxf(v[0] + sSh[co], 0.f); o0.y = fmaxf(v[1] + sSh[co], 0.f);
            o0.z = fmaxf(v[2] + sSh[co], 0.f); o0.w = fmaxf(v[3] + sSh[co], 0.f);
            o1.x = fmaxf(v[4] + sSh[co], 0.f); o1.y = fmaxf(v[5] + sSh[co], 0.f);
            o1.z = fmaxf(v[6] + sSh[co], 0.f); o1.w = fmaxf(v[7] + sSh[co], 0.f);
            float* op = &out[((size_t)(b * COUT + co0 + co) * HH + h0 + yy) * WW + px];
            *(float4*)op = o0;
            *(float4*)(op + 4) = o1;
        }
    } else if (mode == 0) {
#pragma unroll
        for (int co = 0; co < 8; co++) {
            float v[8];
            unpack2(acc[co][0], v[0], v[1]);
            unpack2(acc[co][1], v[2], v[3]);
            unpack2(acc[co][2], v[4], v[5]);
            unpack2(acc[co][3], v[6], v[7]);
#pragma unroll
            for (int p = 0; p < 8; p++) {
                float y = fmaxf(v[p] + sSh[co], 0.f);
                atomicMax(&sMax[co][px + p], __float_as_int(y));
            }
        }
        __syncthreads();
        int* gout = (int*)out;
        for (int i = tid; i < 1024; i += 128) {
            int co = i >> 7, w = i & 127;
            atomicMax(&gout[(b * MIDC + co0 + co) * WW + w], sMax[co][w]);
        }
    } else {
#pragma unroll
        for (int co = 0; co < 8; co++) {
            float v[8];
            unpack2(acc[co][0], v[0], v[1]);
            unpack2(acc[co][1], v[2], v[3]);
            unpack2(acc[co][2], v[4], v[5]);
            unpack2(acc[co][3], v[6], v[7]);
            float m = v[0];
#pragma unroll
            for (int p = 1; p < 8; p++) m = fmaxf(m, v[p]);
            float y = fmaxf(m + sSh[co], 0.f);
            atomicMax(&sMax[co][yy], __float_as_int(y));
        }
        __syncthreads();
        int* gout = (int*)out;
        if (tid < 64) {
            int co = tid >> 3, h = tid & 7;
            atomicMax(&gout[(b * MIDC + co0 + co) * HH + h0 + h], sMax[co][h]);
        }
    }
}

// Fused merge: r = relu( bn_p(conv3x3(s, p_w)) + bn_c1(conv1x1(x, c1_w)) )
// s[b,c,h,w] = colmax[b,c,w] + rowmax[b,c,h], materialized per-tile in smem.
__global__ __launch_bounds__(128)
void merge_kernel(const float* __restrict__ x,
                  const float* __restrict__ pw, const float* __restrict__ pg,
                  const float* __restrict__ pb, const float* __restrict__ pm,
                  const float* __restrict__ pv,
                  const float* __restrict__ c1w, const float* __restrict__ c1g,
                  const float* __restrict__ c1b, const float* __restrict__ c1m,
                  const float* __restrict__ c1v)
{
    __shared__ float sBuf[4 * 10 * 132];     // phase A: 4x8x128 ; phase B: 4x10x132
    __shared__ ulonglong2 sWp[8][4][3];
    __shared__ u64 sW2[8][4][3];
    __shared__ u64 sW1[8][4];
    __shared__ float sScP[8], sScC[8], sSh[8];

    const int h0 = blockIdx.x * 8;
    const int co0 = blockIdx.y * 8;
    const int b = blockIdx.z;
    const int xx = threadIdx.x, yy = threadIdx.y;
    const int tid = yy * 16 + xx;
    const int px = xx * 8;

    if (tid < 8) {
        int c = co0 + tid;
        float scp = pg[c] * rsqrtf(pv[c] + EPSV);
        float scc = c1g[c] * rsqrtf(c1v[c] + EPSV);
        sScP[tid] = scp;
        sScC[tid] = scc;
        sSh[tid] = (pb[c] - pm[c] * scp) + (c1b[c] - c1m[c] * scc);
    }
    __syncthreads();

    u64 acc[8][4];
#pragma unroll
    for (int co = 0; co < 8; co++)
#pragma unroll
        for (int q = 0; q < 4; q++) acc[co][q] = 0ULL;

    // ---- Phase A: 1x1 conv over x
    const float* xb = x + (size_t)b * DIMC * HH * WW;
    for (int ci0 = 0; ci0 < DIMC; ci0 += 4) {
        for (int idx = tid; idx < 1024; idx += 128) {   // 4096 floats as float4
            int ci = idx >> 8, r = idx & 255;           // r = hh*32 + (wl/4)
            int hh = r >> 5, w4 = (r & 31) << 2;
            float4 v = *(const float4*)&xb[(size_t)(ci0 + ci) * HH * WW + (h0 + hh) * WW + w4];
            *(float4*)&sBuf[ci * 1024 + hh * 128 + w4] = v;
        }
        if (tid < 32) {
            int co = tid >> 2, ci = tid & 3;
            float w = c1w[(size_t)(co0 + co) * DIMC + ci0 + ci] * sScC[co];
            sW1[co][ci] = pack2(w, w);
        }
        __syncthreads();
        for (int ci = 0; ci < 4; ci++) {
            const float* rp = &sBuf[ci * 1024 + yy * 128 + px];
            float4 va = *(const float4*)rp;
            float4 vb = *(const float4*)(rp + 4);
            u64 a[4];
            a[0] = pack2(va.x, va.y); a[1] = pack2(va.z, va.w);
            a[2] = pack2(vb.x, vb.y); a[3] = pack2(vb.z, vb.w);
#pragma unroll
            for (int co = 0; co < 8; co++) {
                u64 wv = sW1[co][ci];
#pragma unroll
                for (int q = 0; q < 4; q++) fma2(acc[co][q], wv, a[q]);
            }
        }
        __syncthreads();
    }

    // ---- Phase B: 3x3 conv over s (materialized tile, boundary zeros in fill)
    for (int ci0 = 0; ci0 < MIDC; ci0 += 4) {
        for (int idx = tid; idx < 5280; idx += 128) {
            int ci = idx / 1320, r = idx % 1320;
            int hh = r / 132, c = r % 132;
            int gh = h0 - 1 + hh, gw = c - 1;
            float v = 0.f;
            if ((unsigned)gh < (unsigned)HH && (unsigned)gw < (unsigned)WW)
                v = g_colmax[(b * MIDC + ci0 + ci) * WW + gw]
                  + g_rowmax[(b * MIDC + ci0 + ci) * HH + gh];
            sBuf[idx] = v;
        }
        for (int idx = tid; idx < 288; idx += 128) {
            int co = idx / 36, r = idx % 36, ci = r / 9, k = r % 9;
            int dy = k / 3, dx = k % 3;
            float w = pw[((size_t)(co0 + co) * MIDC + ci0 + ci) * 9 + k] * sScP[co];
            u64 d = pack2(w, w);
            if (dx == 2) sW2[co][ci][dy] = d;
            else ((u64*)&sWp[co][ci][dy])[dx] = d;
        }
        __syncthreads();

        for (int ci = 0; ci < 4; ci++) {
#pragma unroll
            for (int dy = 0; dy < 3; dy++) {
                const float* rp = &sBuf[ci * 1320 + (yy + dy) * 132 + px];
                float4 va = *(const float4*)rp;
                float4 vb = *(const float4*)(rp + 4);
                float2 vc = *(const float2*)(rp + 8);
                u64 a0[4], a1[4], a2[4];
                a0[0] = pack2(va.x, va.y); a0[1] = pack2(va.z, va.w);
                a0[2] = pack2(vb.x, vb.y); a0[3] = pack2(vb.z, vb.w);
                a1[0] = pack2(va.y, va.z); a1[1] = pack2(va.w, vb.x);
                a1[2] = pack2(vb.y, vb.z); a1[3] = pack2(vb.w, vc.x);
                a2[0] = pack2(va.z, va.w); a2[1] = pack2(vb.x, vb.y);
                a2[2] = pack2(vb.z, vb.w); a2[3] = pack2(vc.x, vc.y);
#pragma unroll
                for (int co = 0; co < 8; co++) {
                    ulonglong2 wp = sWp[co][ci][dy];
                    u64 w2 = sW2[co][ci][dy];
#pragma unroll
                    for (int q = 0; q < 4; q++) {
                        fma2(acc[co][q], wp.x, a0[q]);
                        fma2(acc[co][q], wp.y, a1[q]);
                        fma2(acc[co][q], w2, a2[q]);
                    }
                }
            }
        }
        __syncthreads();
    }

    // epilogue
#pragma unroll
    for (int co = 0; co < 8; co++) {
        float v[8];
        unpack2(acc[co][0], v[0], v[1]);
        unpack2(acc[co][1], v[2], v[3]);
        unpack2(acc[co][2], v[4], v[5]);
        unpack2(acc[co][3], v[6], v[7]);
        float4 o0, o1;
        o0.x = fmaxf(v[0] + sSh[co], 0.f); o0.y = fmaxf(v[1] + sSh[co], 0.f);
        o0.z = fmaxf(v[2] + sSh[co], 0.f); o0.w = fmaxf(v[3] + sSh[co], 0.f);
        o1.x = fmaxf(v[4] + sSh[co], 0.f); o1.y = fmaxf(v[5] + sSh[co], 0.f);
        o1.z = fmaxf(v[6] + sSh[co], 0.f); o1.w = fmaxf(v[7] + sSh[co], 0.f);
        float* op = &g_r[((size_t)(b * DIMC + co0 + co) * HH + h0 + yy) * WW + px];
        *(float4*)op = o0;
        *(float4*)(op + 4) = o1;
    }
}

extern "C" void kernel_launch(void* const* d_in, const int* in_sizes, int n_in,
                              void* d_out, int out_size)
{
    const float* x    = (const float*)d_in[0];
    const float* p1w  = (const float*)d_in[1];
    const float* p1g  = (const float*)d_in[2];
    const float* p1b  = (const float*)d_in[3];
    const float* p1m  = (const float*)d_in[4];
    const float* p1v  = (const float*)d_in[5];
    const float* p2w  = (const float*)d_in[6];
    const float* p2g  = (const float*)d_in[7];
    const float* p2b  = (const float*)d_in[8];
    const float* p2m  = (const float*)d_in[9];
    const float* p2v  = (const float*)d_in[10];
    const float* pw   = (const float*)d_in[11];
    const float* pg   = (const float*)d_in[12];
    const float* pb   = (const float*)d_in[13];
    const float* pm   = (const float*)d_in[14];
    const float* pv   = (const float*)d_in[15];
    const float* c1w  = (const float*)d_in[16];
    const float* c1g  = (const float*)d_in[17];
    const float* c1b  = (const float*)d_in[18];
    const float* c1m  = (const float*)d_in[19];
    const float* c1v  = (const float*)d_in[20];
    const float* c2w  = (const float*)d_in[21];
    const float* c2g  = (const float*)d_in[22];
    const float* c2b  = (const float*)d_in[23];
    const float* c2m  = (const float*)d_in[24];
    const float* c2v  = (const float*)d_in[25];

    float* colmax;  cudaGetSymbolAddress((void**)&colmax, g_colmax);
    float* rowmax;  cudaGetSymbolAddress((void**)&rowmax, g_rowmax);
    float* rbuf;    cudaGetSymbolAddress((void**)&rbuf, g_r);

    dim3 blk(16, 8);

    init_max_kernel<<<256, 256>>>();

    conv3_kernel<<<dim3(16, MIDC / 8, BATCH), blk>>>(
        x, p1w, p1g, p1b, p1m, p1v, DIMC, MIDC, 0, colmax);

    conv3_kernel<<<dim3(16, MIDC / 8, BATCH), blk>>>(
        x, p2w, p2g, p2b, p2m, p2v, DIMC, MIDC, 1, rowmax);

    merge_kernel<<<dim3(16, DIMC / 8, BATCH), blk>>>(
        x, pw, pg, pb, pm, pv, c1w, c1g, c1b, c1m, c1v);

    conv3_kernel<<<dim3(16, DIMC / 8, BATCH), blk>>>(
        rbuf, c2w, c2g, c2b, c2m, c2v, DIMC, DIMC, 2, (float*)d_out);
}

// round 4
// speedup vs baseline: 1.0014x; 1.0014x over previous
#include <cuda_runtime.h>

#define BATCH 4
#define DIMC 256
#define MIDC 128
#define HH 128
#define WW 128
#define EPSV 1e-5f

typedef unsigned long long u64;

__device__ __forceinline__ u64 pack2(float lo, float hi) {
    u64 r;
    asm("mov.b64 %0, {%1, %2};" : "=l"(r) : "f"(lo), "f"(hi));
    return r;
}
__device__ __forceinline__ void unpack2(u64 v, float& lo, float& hi) {
    asm("mov.b64 {%0, %1}, %2;" : "=f"(lo), "=f"(hi) : "l"(v));
}
__device__ __forceinline__ void fma2(u64& d, u64 a, u64 b) {
    asm("fma.rn.f32x2 %0, %1, %2, %0;" : "+l"(d) : "l"(a), "l"(b));
}

// Scratch (device globals: allocation-free)
__device__ float g_colmax[BATCH * MIDC * WW];
__device__ float g_rowmax[BATCH * MIDC * HH];
__device__ float g_r[(size_t)BATCH * DIMC * HH * WW];

__global__ void init_max_kernel() {
    int i = blockIdx.x * blockDim.x + threadIdx.x;
    if (i < BATCH * MIDC * WW) {
        g_colmax[i] = 0.f;
        g_rowmax[i] = 0.f;
    }
}

// 3x3 conv (pad=1) + BN + ReLU. Tile: 8 rows x 128 cols, 8 couts per block.
// Each thread: 8 contiguous pixels x 8 couts (32 u64 f32x2 accumulators).
// mode 0: column max (over h) -> out ; mode 1: row max (over w) -> out ;
// mode 2: store NCHW.
__global__ __launch_bounds__(128)
void conv3_kernel(const float* __restrict__ in, const float* __restrict__ wgt,
                  const float* __restrict__ gamma, const float* __restrict__ beta,
                  const float* __restrict__ mean, const float* __restrict__ var,
                  int CIN, int COUT, int mode, float* __restrict__ out)
{
    __shared__ float sIn[4 * 10 * 132];          // 4 ci x 10 rows x 132 (halo+pad)
    __shared__ ulonglong2 sWp[8][4][3];          // (dx0,dx1) dup-u64 pairs
    __shared__ u64 sW2[8][4][3];                 // dx2
    __shared__ float sSc[8], sSh[8];
    __shared__ int sMax[8][128];

    const int h0 = blockIdx.x * 8;
    const int co0 = blockIdx.y * 8;
    const int b = blockIdx.z;
    const int xx = threadIdx.x, yy = threadIdx.y;
    const int tid = yy * 16 + xx;
    const int px = xx * 8;   // first pixel (w) handled by this thread

    if (tid < 8) {
        int c = co0 + tid;
        float sc = gamma[c] * rsqrtf(var[c] + EPSV);
        sSc[tid] = sc;
        sSh[tid] = beta[c] - mean[c] * sc;
    }
    for (int i = tid; i < 1024; i += 128) ((int*)sMax)[i] = 0;
    __syncthreads();

    u64 acc[8][4];
#pragma unroll
    for (int co = 0; co < 8; co++)
#pragma unroll
        for (int q = 0; q < 4; q++) acc[co][q] = 0ULL;

    const float* inb = in + (size_t)b * CIN * HH * WW;

    for (int ci0 = 0; ci0 < CIN; ci0 += 4) {
        // input tile fill (scalar, predicated zero halo)
        for (int idx = tid; idx < 5280; idx += 128) {
            int ci = idx / 1320, r = idx % 1320;
            int hh = r / 132, c = r % 132;
            int gh = h0 - 1 + hh, gw = c - 1;
            float v = 0.f;
            if ((unsigned)gh < (unsigned)HH && (unsigned)gw < (unsigned)WW)
                v = inb[(size_t)(ci0 + ci) * HH * WW + gh * WW + gw];
            sIn[idx] = v;
        }
        // weights (BN-scaled, duplicated halves, pair layout)
        for (int idx = tid; idx < 288; idx += 128) {
            int co = idx / 36, r = idx % 36, ci = r / 9, k = r % 9;
            int dy = k / 3, dx = k % 3;
            float w = wgt[((size_t)(co0 + co) * CIN + ci0 + ci) * 9 + k] * sSc[co];
            u64 d = pack2(w, w);
            if (dx == 2) sW2[co][ci][dy] = d;
            else ((u64*)&sWp[co][ci][dy])[dx] = d;
        }
        __syncthreads();

        for (int ci = 0; ci < 4; ci++) {
#pragma unroll
            for (int dy = 0; dy < 3; dy++) {
                const float* rp = &sIn[ci * 1320 + (yy + dy) * 132 + px];
                float4 va = *(const float4*)rp;
                float4 vb = *(const float4*)(rp + 4);
                float2 vc = *(const float2*)(rp + 8);
                u64 a0[4], a1[4], a2[4];
                a0[0] = pack2(va.x, va.y); a0[1] = pack2(va.z, va.w);
                a0[2] = pack2(vb.x, vb.y); a0[3] = pack2(vb.z, vb.w);
                a1[0] = pack2(va.y, va.z); a1[1] = pack2(va.w, vb.x);
                a1[2] = pack2(vb.y, vb.z); a1[3] = pack2(vb.w, vc.x);
                a2[0] = pack2(va.z, va.w); a2[1] = pack2(vb.x, vb.y);
                a2[2] = pack2(vb.z, vb.w); a2[3] = pack2(vc.x, vc.y);
#pragma unroll
                for (int co = 0; co < 8; co++) {
                    ulonglong2 wp = sWp[co][ci][dy];
                    u64 w2 = sW2[co][ci][dy];
#pragma unroll
                    for (int q = 0; q < 4; q++) {
                        fma2(acc[co][q], wp.x, a0[q]);
                        fma2(acc[co][q], wp.y, a1[q]);
                        fma2(acc[co][q], w2, a2[q]);
                    }
                }
            }
        }
        __syncthreads();
    }

    if (mode == 2) {
#pragma unroll
        for (int co = 0; co < 8; co++) {
            float v[8];
            unpack2(acc[co][0], v[0], v[1]);
            unpack2(acc[co][1], v[2], v[3]);
            unpack2(acc[co][2], v[4], v[5]);
            unpack2(acc[co][3], v[6], v[7]);
            float4 o0, o1;
            o0.x = fmaxf(v[0] + sSh[co], 0.f); o0.y = fmaxf(v[1] + sSh[co], 0.f);
            o0.z = fmaxf(v[2] + sSh[co], 0.f); o0.w = fmaxf(v[3] + sSh[co], 0.f);
            o1.x = fmaxf(v[4] + sSh[co], 0.f); o1.y = fmaxf(v[5] + sSh[co], 0.f);
            o1.z = fmaxf(v[6] + sSh[co], 0.f); o1.w = fmaxf(v[7] + sSh[co], 0.f);
            float* op = &out[((size_t)(b * COUT + co0 + co) * HH + h0 + yy) * WW + px];
            *(float4*)op = o0;
            *(float4*)(op + 4) = o1;
        }
    } else if (mode == 0) {
#pragma unroll
        for (int co = 0; co < 8; co++) {
            float v[8];
            unpack2(acc[co][0], v[0], v[1]);
            unpack2(acc[co][1], v[2], v[3]);
            unpack2(acc[co][2], v[4], v[5]);
            unpack2(acc[co][3], v[6], v[7]);
#pragma unroll
            for (int p = 0; p < 8; p++) {
                float y = fmaxf(v[p] + sSh[co], 0.f);
                atomicMax(&sMax[co][px + p], __float_as_int(y));
            }
        }
        __syncthreads();
        int* gout = (int*)out;
        for (int i = tid; i < 1024; i += 128) {
            int co = i >> 7, w = i & 127;
            atomicMax(&gout[(b * MIDC + co0 + co) * WW + w], sMax[co][w]);
        }
    } else {
#pragma unroll
        for (int co = 0; co < 8; co++) {
            float v[8];
            unpack2(acc[co][0], v[0], v[1]);
            unpack2(acc[co][1], v[2], v[3]);
            unpack2(acc[co][2], v[4], v[5]);
            unpack2(acc[co][3], v[6], v[7]);
            float m = v[0];
#pragma unroll
            for (int p = 1; p < 8; p++) m = fmaxf(m, v[p]);
            float y = fmaxf(m + sSh[co], 0.f);
            atomicMax(&sMax[co][yy], __float_as_int(y));
        }
        __syncthreads();
        int* gout = (int*)out;
        if (tid < 64) {
            int co = tid >> 3, h = tid & 7;
            atomicMax(&gout[(b * MIDC + co0 + co) * HH + h0 + h], sMax[co][h]);
        }
    }
}

// Fused merge: r = relu( bn_p(conv3x3(s, p_w)) + bn_c1(conv1x1(x, c1_w)) )
// s[b,c,h,w] = colmax[b,c,w] + rowmax[b,c,h], materialized per-tile in smem.
__global__ __launch_bounds__(128)
void merge_kernel(const float* __restrict__ x,
                  const float* __restrict__ pw, const float* __restrict__ pg,
                  const float* __restrict__ pb, const float* __restrict__ pm,
                  const float* __restrict__ pv,
                  const float* __restrict__ c1w, const float* __restrict__ c1g,
                  const float* __restrict__ c1b, const float* __restrict__ c1m,
                  const float* __restrict__ c1v)
{
    __shared__ float sBuf[4 * 10 * 132];     // phase A: 4x8x128 ; phase B: 4x10x132
    __shared__ ulonglong2 sWp[8][4][3];
    __shared__ u64 sW2[8][4][3];
    __shared__ u64 sW1[8][4];
    __shared__ float sScP[8], sScC[8], sSh[8];

    const int h0 = blockIdx.x * 8;
    const int co0 = blockIdx.y * 8;
    const int b = blockIdx.z;
    const int xx = threadIdx.x, yy = threadIdx.y;
    const int tid = yy * 16 + xx;
    const int px = xx * 8;

    if (tid < 8) {
        int c = co0 + tid;
        float scp = pg[c] * rsqrtf(pv[c] + EPSV);
        float scc = c1g[c] * rsqrtf(c1v[c] + EPSV);
        sScP[tid] = scp;
        sScC[tid] = scc;
        sSh[tid] = (pb[c] - pm[c] * scp) + (c1b[c] - c1m[c] * scc);
    }
    __syncthreads();

    u64 acc[8][4];
#pragma unroll
    for (int co = 0; co < 8; co++)
#pragma unroll
        for (int q = 0; q < 4; q++) acc[co][q] = 0ULL;

    // ---- Phase A: 1x1 conv over x
    const float* xb = x + (size_t)b * DIMC * HH * WW;
    for (int ci0 = 0; ci0 < DIMC; ci0 += 4) {
        for (int idx = tid; idx < 1024; idx += 128) {   // 4096 floats as float4
            int ci = idx >> 8, r = idx & 255;           // r = hh*32 + (wl/4)
            int hh = r >> 5, w4 = (r & 31) << 2;
            float4 v = *(const float4*)&xb[(size_t)(ci0 + ci) * HH * WW + (h0 + hh) * WW + w4];
            *(float4*)&sBuf[ci * 1024 + hh * 128 + w4] = v;
        }
        if (tid < 32) {
            int co = tid >> 2, ci = tid & 3;
            float w = c1w[(size_t)(co0 + co) * DIMC + ci0 + ci] * sScC[co];
            sW1[co][ci] = pack2(w, w);
        }
        __syncthreads();
        for (int ci = 0; ci < 4; ci++) {
            const float* rp = &sBuf[ci * 1024 + yy * 128 + px];
            float4 va = *(const float4*)rp;
            float4 vb = *(const float4*)(rp + 4);
            u64 a[4];
            a[0] = pack2(va.x, va.y); a[1] = pack2(va.z, va.w);
            a[2] = pack2(vb.x, vb.y); a[3] = pack2(vb.z, vb.w);
#pragma unroll
            for (int co = 0; co < 8; co++) {
                u64 wv = sW1[co][ci];
#pragma unroll
                for (int q = 0; q < 4; q++) fma2(acc[co][q], wv, a[q]);
            }
        }
        __syncthreads();
    }

    // ---- Phase B: 3x3 conv over s (materialized tile, boundary zeros in fill)
    for (int ci0 = 0; ci0 < MIDC; ci0 += 4) {
        for (int idx = tid; idx < 5280; idx += 128) {
            int ci = idx / 1320, r = idx % 1320;
            int hh = r / 132, c = r % 132;
            int gh = h0 - 1 + hh, gw = c - 1;
            float v = 0.f;
            if ((unsigned)gh < (unsigned)HH && (unsigned)gw < (unsigned)WW)
                v = g_colmax[(b * MIDC + ci0 + ci) * WW + gw]
                  + g_rowmax[(b * MIDC + ci0 + ci) * HH + gh];
            sBuf[idx] = v;
        }
        for (int idx = tid; idx < 288; idx += 128) {
            int co = idx / 36, r = idx % 36, ci = r / 9, k = r % 9;
            int dy = k / 3, dx = k % 3;
            float w = pw[((size_t)(co0 + co) * MIDC + ci0 + ci) * 9 + k] * sScP[co];
            u64 d = pack2(w, w);
            if (dx == 2) sW2[co][ci][dy] = d;
            else ((u64*)&sWp[co][ci][dy])[dx] = d;
        }
        __syncthreads();

        for (int ci = 0; ci < 4; ci++) {
#pragma unroll
            for (int dy = 0; dy < 3; dy++) {
                const float* rp = &sBuf[ci * 1320 + (yy + dy) * 132 + px];
                float4 va = *(const float4*)rp;
                float4 vb = *(const float4*)(rp + 4);
                float2 vc = *(const float2*)(rp + 8);
                u64 a0[4], a1[4], a2[4];
                a0[0] = pack2(va.x, va.y); a0[1] = pack2(va.z, va.w);
                a0[2] = pack2(vb.x, vb.y); a0[3] = pack2(vb.z, vb.w);
                a1[0] = pack2(va.y, va.z); a1[1] = pack2(va.w, vb.x);
                a1[2] = pack2(vb.y, vb.z); a1[3] = pack2(vb.w, vc.x);
                a2[0] = pack2(va.z, va.w); a2[1] = pack2(vb.x, vb.y);
                a2[2] = pack2(vb.z, vb.w); a2[3] = pack2(vc.x, vc.y);
#pragma unroll
                for (int co = 0; co < 8; co++) {
                    ulonglong2 wp = sWp[co][ci][dy];
                    u64 w2 = sW2[co][ci][dy];
#pragma unroll
                    for (int q = 0; q < 4; q++) {
                        fma2(acc[co][q], wp.x, a0[q]);
                        fma2(acc[co][q], wp.y, a1[q]);
                        fma2(acc[co][q], w2, a2[q]);
                    }
                }
            }
        }
        __syncthreads();
    }

    // epilogue
#pragma unroll
    for (int co = 0; co < 8; co++) {
        float v[8];
        unpack2(acc[co][0], v[0], v[1]);
        unpack2(acc[co][1], v[2], v[3]);
        unpack2(acc[co][2], v[4], v[5]);
        unpack2(acc[co][3], v[6], v[7]);
        float4 o0, o1;
        o0.x = fmaxf(v[0] + sSh[co], 0.f); o0.y = fmaxf(v[1] + sSh[co], 0.f);
        o0.z = fmaxf(v[2] + sSh[co], 0.f); o0.w = fmaxf(v[3] + sSh[co], 0.f);
        o1.x = fmaxf(v[4] + sSh[co], 0.f); o1.y = fmaxf(v[5] + sSh[co], 0.f);
        o1.z = fmaxf(v[6] + sSh[co], 0.f); o1.w = fmaxf(v[7] + sSh[co], 0.f);
        float* op = &g_r[((size_t)(b * DIMC + co0 + co) * HH + h0 + yy) * WW + px];
        *(float4*)op = o0;
        *(float4*)(op + 4) = o1;
    }
}

extern "C" void kernel_launch(void* const* d_in, const int* in_sizes, int n_in,
                              void* d_out, int out_size)
{
    const float* x    = (const float*)d_in[0];
    const float* p1w  = (const float*)d_in[1];
    const float* p1g  = (const float*)d_in[2];
    const float* p1b  = (const float*)d_in[3];
    const float* p1m  = (const float*)d_in[4];
    const float* p1v  = (const float*)d_in[5];
    const float* p2w  = (const float*)d_in[6];
    const float* p2g  = (const float*)d_in[7];
    const float* p2b  = (const float*)d_in[8];
    const float* p2m  = (const float*)d_in[9];
    const float* p2v  = (const float*)d_in[10];
    const float* pw   = (const float*)d_in[11];
    const float* pg   = (const float*)d_in[12];
    const float* pb   = (const float*)d_in[13];
    const float* pm   = (const float*)d_in[14];
    const float* pv   = (const float*)d_in[15];
    const float* c1w  = (const float*)d_in[16];
    const float* c1g  = (const float*)d_in[17];
    const float* c1b  = (const float*)d_in[18];
    const float* c1m  = (const float*)d_in[19];
    const float* c1v  = (const float*)d_in[20];
    const float* c2w  = (const float*)d_in[21];
    const float* c2g  = (const float*)d_in[22];
    const float* c2b  = (const float*)d_in[23];
    const float* c2m  = (const float*)d_in[24];
    const float* c2v  = (const float*)d_in[25];

    float* colmax;  cudaGetSymbolAddress((void**)&colmax, g_colmax);
    float* rowmax;  cudaGetSymbolAddress((void**)&rowmax, g_rowmax);
    float* rbuf;    cudaGetSymbolAddress((void**)&rbuf, g_r);

    dim3 blk(16, 8);

    init_max_kernel<<<256, 256>>>();

    conv3_kernel<<<dim3(16, MIDC / 8, BATCH), blk>>>(
        x, p1w, p1g, p1b, p1m, p1v, DIMC, MIDC, 0, colmax);

    conv3_kernel<<<dim3(16, MIDC / 8, BATCH), blk>>>(
        x, p2w, p2g, p2b, p2m, p2v, DIMC, MIDC, 1, rowmax);

    merge_kernel<<<dim3(16, DIMC / 8, BATCH), blk>>>(
        x, pw, pg, pb, pm, pv, c1w, c1g, c1b, c1m, c1v);

    conv3_kernel<<<dim3(16, DIMC / 8, BATCH), blk>>>(
        rbuf, c2w, c2g, c2b, c2m, c2v, DIMC, DIMC, 2, (float*)d_out);
}